// round 16
// baseline (speedup 1.0000x reference)
#include <cuda_runtime.h>
#include <cstdint>

#define L_DIM 2048
#define B_DIM 64
#define D_DEC 1024
#define D_ALIGN 512
#define D_ENC 1024
#define N_SPLIT 16
#define L_PER_SPLIT (L_DIM / N_SPLIT)   // 128
#define K_SPLIT 4
#define K_CHUNK (D_DEC / K_SPLIT)       // 256

// ---- scratch ----
__device__ float g_proj_part[K_SPLIT][B_DIM * D_ALIGN];  // 512 KB
__device__ float g_score[L_DIM * B_DIM];
__device__ float g_m[N_SPLIT * B_DIM];
__device__ float g_z[N_SPLIT * B_DIM];
__device__ float g_partial[N_SPLIT * B_DIM * D_ENC];     // 4 MB
__device__ float2 g_stats[B_DIM];                        // {m_global, 1/Z}

__device__ __forceinline__ float tanh_approx(float x) {
    float y;
    asm("tanh.approx.f32 %0, %1;" : "=f"(y) : "f"(x));
    return y;
}

__device__ __forceinline__ float4 ldcs4(const float4* p) {
    float4 v;
    asm("ld.global.cs.v4.f32 {%0,%1,%2,%3}, [%4];"
        : "=f"(v.x), "=f"(v.y), "=f"(v.z), "=f"(v.w) : "l"(p));
    return v;
}

// ---- Kernel 1: split-K partial proj, thread-per-output (R9 shape) ----
__global__ __launch_bounds__(256) void k_projp(const float* __restrict__ s_tm1,
                                               const float* __restrict__ sa_w) {
    __shared__ float4 sw[32][(K_CHUNK / 4) + 1];
    __shared__ float4 ss[8][(K_CHUNK / 4) + 1];
    int a0 = blockIdx.x * 32, b0 = blockIdx.y * 8;
    int k0 = blockIdx.z * K_CHUNK;
    for (int i = threadIdx.x; i < 32 * (K_CHUNK / 4); i += 256) {
        int r = i >> 6, c = i & 63;
        sw[r][c] = ((const float4*)(sa_w + (size_t)(a0 + r) * D_DEC + k0))[c];
    }
    for (int i = threadIdx.x; i < 8 * (K_CHUNK / 4); i += 256) {
        int r = i >> 6, c = i & 63;
        ss[r][c] = ((const float4*)(s_tm1 + (size_t)(b0 + r) * D_DEC + k0))[c];
    }
    __syncthreads();
    int al = threadIdx.x >> 3, bl = threadIdx.x & 7;
    float acc0 = 0.f, acc1 = 0.f;
#pragma unroll 8
    for (int j = 0; j < K_CHUNK / 4; j += 2) {
        float4 w0 = sw[al][j];
        float4 s0 = ss[bl][j];
        float4 w1 = sw[al][j + 1];
        float4 s1 = ss[bl][j + 1];
        acc0 = fmaf(w0.x, s0.x, acc0);
        acc0 = fmaf(w0.y, s0.y, acc0);
        acc0 = fmaf(w0.z, s0.z, acc0);
        acc0 = fmaf(w0.w, s0.w, acc0);
        acc1 = fmaf(w1.x, s1.x, acc1);
        acc1 = fmaf(w1.y, s1.y, acc1);
        acc1 = fmaf(w1.z, s1.z, acc1);
        acc1 = fmaf(w1.w, s1.w, acc1);
    }
    g_proj_part[blockIdx.z][(b0 + bl) * D_ALIGN + a0 + al] = acc0 + acc1;
}

// ---- Kernel 2 (fused, mask-skipping + split Z; phase 1 = 2 l's per warp) ----
__global__ __launch_bounds__(256) void k_fused(const float* __restrict__ uh,
                                               const float* __restrict__ sa_b,
                                               const float* __restrict__ a1_w,
                                               const float* __restrict__ a1_b,
                                               const float* __restrict__ xs_mask,
                                               const float* __restrict__ xs_h) {
    __shared__ float4 s_proj[D_ALIGN / 4];
    __shared__ float4 s_w[D_ALIGN / 4];
    __shared__ int   s_list[L_PER_SPLIT];
    __shared__ float s_sc[L_PER_SPLIT];
    __shared__ float s_wt[L_PER_SPLIT];
    __shared__ float red[128];
    __shared__ int s_wcnt[4];
    __shared__ unsigned s_ball[4];
    int s = blockIdx.x, b = blockIdx.y;
    int tid = threadIdx.x;
    int l0 = s * L_PER_SPLIT;

    for (int i = tid; i < D_ALIGN / 4; i += 256) {
        float4 p0 = ((const float4*)(g_proj_part[0] + b * D_ALIGN))[i];
        float4 p1 = ((const float4*)(g_proj_part[1] + b * D_ALIGN))[i];
        float4 p2 = ((const float4*)(g_proj_part[2] + b * D_ALIGN))[i];
        float4 p3 = ((const float4*)(g_proj_part[3] + b * D_ALIGN))[i];
        float4 sb = ((const float4*)sa_b)[i];
        s_proj[i] = make_float4((((p0.x + p1.x) + p2.x) + p3.x) + sb.x,
                                (((p0.y + p1.y) + p2.y) + p3.y) + sb.y,
                                (((p0.z + p1.z) + p2.z) + p3.z) + sb.z,
                                (((p0.w + p1.w) + p2.w) + p3.w) + sb.w);
        s_w[i] = ((const float4*)a1_w)[i];
    }

    // mask compaction (deterministic ascending)
    if (tid < 128) {
        int warp4 = tid >> 5, lane = tid & 31;
        float mk = xs_mask[(l0 + tid) * B_DIM + b];
        unsigned ball = __ballot_sync(0xFFFFFFFFu, mk > 0.0f);
        if (lane == 0) {
            s_wcnt[warp4] = __popc(ball);
            s_ball[warp4] = ball;
        }
    }
    __syncthreads();
    int nv = s_wcnt[0] + s_wcnt[1] + s_wcnt[2] + s_wcnt[3];
    if (tid < 128) {
        int warp4 = tid >> 5, lane = tid & 31;
        unsigned ball = s_ball[warp4];
        if ((ball >> lane) & 1u) {
            int off = 0;
#pragma unroll
            for (int w = 0; w < 4; w++) off += (w < warp4) ? s_wcnt[w] : 0;
            int pos = off + __popc(ball & ((1u << lane) - 1u));
            s_list[pos] = tid;
        }
    }
    __syncthreads();

    int warp = tid >> 5, lane = tid & 31;
    float bias = a1_b[0];

    // Phase 1: two l's per warp — 8 independent LDGs in flight per warp
    int iters = (nv + 15) >> 4;
    for (int it = 0; it < iters; it++) {
        int j0 = it * 16 + warp;
        int j1 = j0 + 8;
        if (j0 < nv) {
            bool v1 = (j1 < nv);
            const float4* row0 =
                (const float4*)(uh + ((size_t)((l0 + s_list[j0]) * B_DIM + b)) * D_ALIGN);
            const float4* row1 = v1
                ? (const float4*)(uh + ((size_t)((l0 + s_list[j1]) * B_DIM + b)) * D_ALIGN)
                : row0;
            float sum0 = 0.0f, sum1 = 0.0f;
#pragma unroll
            for (int jj = 0; jj < 4; jj++) {
                int a4 = lane + jj * 32;
                float4 u0 = ldcs4(row0 + a4);
                float4 u1 = ldcs4(row1 + a4);
                float4 p = s_proj[a4];
                float4 w = s_w[a4];
                sum0 = fmaf(tanh_approx(p.x + u0.x), w.x, sum0);
                sum0 = fmaf(tanh_approx(p.y + u0.y), w.y, sum0);
                sum0 = fmaf(tanh_approx(p.z + u0.z), w.z, sum0);
                sum0 = fmaf(tanh_approx(p.w + u0.w), w.w, sum0);
                sum1 = fmaf(tanh_approx(p.x + u1.x), w.x, sum1);
                sum1 = fmaf(tanh_approx(p.y + u1.y), w.y, sum1);
                sum1 = fmaf(tanh_approx(p.z + u1.z), w.z, sum1);
                sum1 = fmaf(tanh_approx(p.w + u1.w), w.w, sum1);
            }
#pragma unroll
            for (int o = 16; o > 0; o >>= 1) {
                sum0 += __shfl_xor_sync(0xFFFFFFFFu, sum0, o);
                sum1 += __shfl_xor_sync(0xFFFFFFFFu, sum1, o);
            }
            if (lane == 0) {
                s_sc[j0] = sum0 + bias;
                if (v1) s_sc[j1] = sum1 + bias;
            }
        }
    }
    __syncthreads();

    // split-local max
    if (tid < 128) red[tid] = (tid < nv) ? s_sc[tid] : -1e30f;
    __syncthreads();
#pragma unroll
    for (int o = 64; o > 0; o >>= 1) {
        if (tid < o) red[tid] = fmaxf(red[tid], red[tid + o]);
        __syncthreads();
    }
    float m_s = red[0];
    __syncthreads();
    if (tid < nv) {
        float sc = s_sc[tid];
        s_wt[tid] = __expf(sc - m_s);
        g_score[(l0 + s_list[tid]) * B_DIM + b] = sc;
    }
    // split-local Z
    if (tid < 128) red[tid] = (tid < nv) ? __expf(s_sc[tid] - m_s) : 0.0f;
    __syncthreads();
#pragma unroll
    for (int o = 64; o > 0; o >>= 1) {
        if (tid < o) red[tid] += red[tid + o];
        __syncthreads();
    }
    if (tid == 0) {
        g_m[s * B_DIM + b] = m_s;
        g_z[s * B_DIM + b] = red[0];
    }
    __syncthreads();

    // Phase 2: weighted accumulation over valid xs_h rows, 4-deep batches
    float4 acc = make_float4(0.f, 0.f, 0.f, 0.f);
    const float4* base = (const float4*)xs_h;
    const size_t stride = (size_t)B_DIM * (D_ENC / 4);
    size_t rowbase = ((size_t)(l0 * B_DIM + b)) * (D_ENC / 4) + tid;
    int j = 0;
    for (; j + 3 < nv; j += 4) {
        int i0 = s_list[j], i1 = s_list[j + 1], i2 = s_list[j + 2], i3 = s_list[j + 3];
        float4 v0 = ldcs4(base + rowbase + (size_t)i0 * stride);
        float4 v1 = ldcs4(base + rowbase + (size_t)i1 * stride);
        float4 v2 = ldcs4(base + rowbase + (size_t)i2 * stride);
        float4 v3 = ldcs4(base + rowbase + (size_t)i3 * stride);
        float w0 = s_wt[j], w1 = s_wt[j + 1], w2 = s_wt[j + 2], w3 = s_wt[j + 3];
        acc.x = fmaf(w0, v0.x, acc.x); acc.y = fmaf(w0, v0.y, acc.y);
        acc.z = fmaf(w0, v0.z, acc.z); acc.w = fmaf(w0, v0.w, acc.w);
        acc.x = fmaf(w1, v1.x, acc.x); acc.y = fmaf(w1, v1.y, acc.y);
        acc.z = fmaf(w1, v1.z, acc.z); acc.w = fmaf(w1, v1.w, acc.w);
        acc.x = fmaf(w2, v2.x, acc.x); acc.y = fmaf(w2, v2.y, acc.y);
        acc.z = fmaf(w2, v2.z, acc.z); acc.w = fmaf(w2, v2.w, acc.w);
        acc.x = fmaf(w3, v3.x, acc.x); acc.y = fmaf(w3, v3.y, acc.y);
        acc.z = fmaf(w3, v3.z, acc.z); acc.w = fmaf(w3, v3.w, acc.w);
    }
    for (; j < nv; j++) {
        float4 v = ldcs4(base + rowbase + (size_t)s_list[j] * stride);
        float w = s_wt[j];
        acc.x = fmaf(w, v.x, acc.x); acc.y = fmaf(w, v.y, acc.y);
        acc.z = fmaf(w, v.z, acc.z); acc.w = fmaf(w, v.w, acc.w);
    }
    ((float4*)g_partial)[((s * B_DIM + b) * (D_ENC / 4)) + tid] = acc;
}

// ---- Kernel 3a: tiny per-b stats combine from split (m_s, z_s) ----
__global__ __launch_bounds__(64) void k_stats() {
    int b = threadIdx.x;   // 0..63, single block
    float m = -1e30f;
#pragma unroll
    for (int s = 0; s < N_SPLIT; s++) m = fmaxf(m, g_m[s * B_DIM + b]);
    float z = 0.0f;
#pragma unroll
    for (int s = 0; s < N_SPLIT; s++)
        z += g_z[s * B_DIM + b] * __expf(g_m[s * B_DIM + b] - m);
    g_stats[b] = make_float2(m, 1.0f / z);
}

// ---- Kernel 3b: coalesced write — e_ij (linear blocks) and attend ----
__global__ __launch_bounds__(256) void k_write(const float* __restrict__ xs_mask,
                                               float* __restrict__ out) {
    int t = blockIdx.x;
    int tid = threadIdx.x;
    if (t < (L_DIM * B_DIM) / 256) {
        // coalesced: idx runs linearly over [L, B]
        int idx = t * 256 + tid;
        int b = idx & (B_DIM - 1);
        float2 st = g_stats[b];
        float msk = xs_mask[idx];
        float e = 0.0f;
        if (msk > 0.0f) e = __expf(g_score[idx] - st.x) * st.y;
        out[idx] = e;
    } else {
        // attend: block per b; thread tid -> float4 col; rescale split partials
        int b = t - (L_DIM * B_DIM) / 256;
        float2 st = g_stats[b];
        float m = st.x, inv = st.y;
        float4 acc = make_float4(0.f, 0.f, 0.f, 0.f);
#pragma unroll
        for (int s = 0; s < N_SPLIT; s++) {
            float f = __expf(g_m[s * B_DIM + b] - m);
            float4 v = ((const float4*)g_partial)[((s * B_DIM + b) * (D_ENC / 4)) + tid];
            acc.x = fmaf(f, v.x, acc.x);
            acc.y = fmaf(f, v.y, acc.y);
            acc.z = fmaf(f, v.z, acc.z);
            acc.w = fmaf(f, v.w, acc.w);
        }
        acc.x *= inv; acc.y *= inv; acc.z *= inv; acc.w *= inv;
        ((float4*)(out + L_DIM * B_DIM))[b * (D_ENC / 4) + tid] = acc;
    }
}

extern "C" void kernel_launch(void* const* d_in, const int* in_sizes, int n_in,
                              void* d_out, int out_size) {
    const float* s_tm1   = (const float*)d_in[0];
    const float* xs_h    = (const float*)d_in[1];
    const float* uh      = (const float*)d_in[2];
    const float* xs_mask = (const float*)d_in[3];
    const float* sa_w    = (const float*)d_in[4];
    const float* sa_b    = (const float*)d_in[5];
    const float* a1_w    = (const float*)d_in[6];
    const float* a1_b    = (const float*)d_in[7];
    float* out = (float*)d_out;

    dim3 g1(16, 8, K_SPLIT);
    k_projp<<<g1, 256>>>(s_tm1, sa_w);
    dim3 g2(N_SPLIT, B_DIM);
    k_fused<<<g2, 256>>>(uh, sa_b, a1_w, a1_b, xs_mask, xs_h);
    k_stats<<<1, 64>>>();
    k_write<<<(L_DIM * B_DIM) / 256 + B_DIM, 256>>>(xs_mask, out);
}

// round 17
// speedup vs baseline: 1.0705x; 1.0705x over previous
#include <cuda_runtime.h>
#include <cstdint>

#define L_DIM 2048
#define B_DIM 64
#define D_DEC 1024
#define D_ALIGN 512
#define D_ENC 1024
#define N_SPLIT 16
#define L_PER_SPLIT (L_DIM / N_SPLIT)   // 128
#define K_SPLIT 4
#define K_CHUNK (D_DEC / K_SPLIT)       // 256
#define EW_BLOCKS ((L_DIM * B_DIM) / 256)   // 512 scalar e-write blocks
#define AT_BLOCKS (B_DIM * 4)               // 256 attend blocks

// ---- scratch ----
__device__ float g_proj_part[K_SPLIT][B_DIM * D_ALIGN];  // 512 KB
__device__ float g_score[L_DIM * B_DIM];
__device__ float g_m[N_SPLIT * B_DIM];
__device__ float g_z[N_SPLIT * B_DIM];
__device__ float g_partial[N_SPLIT * B_DIM * D_ENC];     // 4 MB
__device__ float2 g_stats[B_DIM];                        // {m_global, 1/Z}

__device__ __forceinline__ float tanh_approx(float x) {
    float y;
    asm("tanh.approx.f32 %0, %1;" : "=f"(y) : "f"(x));
    return y;
}

__device__ __forceinline__ float4 ldcs4(const float4* p) {
    float4 v;
    asm("ld.global.cs.v4.f32 {%0,%1,%2,%3}, [%4];"
        : "=f"(v.x), "=f"(v.y), "=f"(v.z), "=f"(v.w) : "l"(p));
    return v;
}

// ---- Kernel 1: split-K partial proj, thread-per-output (R9/R13 shape) ----
__global__ __launch_bounds__(256) void k_projp(const float* __restrict__ s_tm1,
                                               const float* __restrict__ sa_w) {
    __shared__ float4 sw[32][(K_CHUNK / 4) + 1];
    __shared__ float4 ss[8][(K_CHUNK / 4) + 1];
    int a0 = blockIdx.x * 32, b0 = blockIdx.y * 8;
    int k0 = blockIdx.z * K_CHUNK;
    for (int i = threadIdx.x; i < 32 * (K_CHUNK / 4); i += 256) {
        int r = i >> 6, c = i & 63;
        sw[r][c] = ((const float4*)(sa_w + (size_t)(a0 + r) * D_DEC + k0))[c];
    }
    for (int i = threadIdx.x; i < 8 * (K_CHUNK / 4); i += 256) {
        int r = i >> 6, c = i & 63;
        ss[r][c] = ((const float4*)(s_tm1 + (size_t)(b0 + r) * D_DEC + k0))[c];
    }
    __syncthreads();
    int al = threadIdx.x >> 3, bl = threadIdx.x & 7;
    float acc0 = 0.f, acc1 = 0.f;
#pragma unroll 8
    for (int j = 0; j < K_CHUNK / 4; j += 2) {
        float4 w0 = sw[al][j];
        float4 s0 = ss[bl][j];
        float4 w1 = sw[al][j + 1];
        float4 s1 = ss[bl][j + 1];
        acc0 = fmaf(w0.x, s0.x, acc0);
        acc0 = fmaf(w0.y, s0.y, acc0);
        acc0 = fmaf(w0.z, s0.z, acc0);
        acc0 = fmaf(w0.w, s0.w, acc0);
        acc1 = fmaf(w1.x, s1.x, acc1);
        acc1 = fmaf(w1.y, s1.y, acc1);
        acc1 = fmaf(w1.z, s1.z, acc1);
        acc1 = fmaf(w1.w, s1.w, acc1);
    }
    g_proj_part[blockIdx.z][(b0 + bl) * D_ALIGN + a0 + al] = acc0 + acc1;
}

// ---- Kernel 2 (fused, mask-skipping + split Z): exact R13 body ----
__global__ __launch_bounds__(256) void k_fused(const float* __restrict__ uh,
                                               const float* __restrict__ sa_b,
                                               const float* __restrict__ a1_w,
                                               const float* __restrict__ a1_b,
                                               const float* __restrict__ xs_mask,
                                               const float* __restrict__ xs_h) {
    __shared__ float4 s_proj[D_ALIGN / 4];
    __shared__ float4 s_w[D_ALIGN / 4];
    __shared__ int   s_list[L_PER_SPLIT];
    __shared__ float s_sc[L_PER_SPLIT];
    __shared__ float s_wt[L_PER_SPLIT];
    __shared__ float red[128];
    __shared__ int s_wcnt[4];
    __shared__ unsigned s_ball[4];
    int s = blockIdx.x, b = blockIdx.y;
    int tid = threadIdx.x;
    int l0 = s * L_PER_SPLIT;

    for (int i = tid; i < D_ALIGN / 4; i += 256) {
        float4 p0 = ((const float4*)(g_proj_part[0] + b * D_ALIGN))[i];
        float4 p1 = ((const float4*)(g_proj_part[1] + b * D_ALIGN))[i];
        float4 p2 = ((const float4*)(g_proj_part[2] + b * D_ALIGN))[i];
        float4 p3 = ((const float4*)(g_proj_part[3] + b * D_ALIGN))[i];
        float4 sb = ((const float4*)sa_b)[i];
        s_proj[i] = make_float4((((p0.x + p1.x) + p2.x) + p3.x) + sb.x,
                                (((p0.y + p1.y) + p2.y) + p3.y) + sb.y,
                                (((p0.z + p1.z) + p2.z) + p3.z) + sb.z,
                                (((p0.w + p1.w) + p2.w) + p3.w) + sb.w);
        s_w[i] = ((const float4*)a1_w)[i];
    }

    // mask compaction (deterministic ascending)
    if (tid < 128) {
        int warp4 = tid >> 5, lane = tid & 31;
        float mk = xs_mask[(l0 + tid) * B_DIM + b];
        unsigned ball = __ballot_sync(0xFFFFFFFFu, mk > 0.0f);
        if (lane == 0) {
            s_wcnt[warp4] = __popc(ball);
            s_ball[warp4] = ball;
        }
    }
    __syncthreads();
    int nv = s_wcnt[0] + s_wcnt[1] + s_wcnt[2] + s_wcnt[3];
    if (tid < 128) {
        int warp4 = tid >> 5, lane = tid & 31;
        unsigned ball = s_ball[warp4];
        if ((ball >> lane) & 1u) {
            int off = 0;
#pragma unroll
            for (int w = 0; w < 4; w++) off += (w < warp4) ? s_wcnt[w] : 0;
            int pos = off + __popc(ball & ((1u << lane) - 1u));
            s_list[pos] = tid;
        }
    }
    __syncthreads();

    int warp = tid >> 5, lane = tid & 31;
    float bias = a1_b[0];

    int iters = (nv + 7) >> 3;
    for (int it = 0; it < iters; it++) {
        int j = it * 8 + warp;
        if (j < nv) {
            int l = l0 + s_list[j];
            const float4* row = (const float4*)(uh + ((size_t)(l * B_DIM + b)) * D_ALIGN);
            float sum = 0.0f;
#pragma unroll
            for (int jj = 0; jj < 4; jj++) {
                int a4 = lane + jj * 32;
                float4 u = ldcs4(row + a4);
                float4 p = s_proj[a4];
                float4 w = s_w[a4];
                sum = fmaf(tanh_approx(p.x + u.x), w.x, sum);
                sum = fmaf(tanh_approx(p.y + u.y), w.y, sum);
                sum = fmaf(tanh_approx(p.z + u.z), w.z, sum);
                sum = fmaf(tanh_approx(p.w + u.w), w.w, sum);
            }
#pragma unroll
            for (int o = 16; o > 0; o >>= 1) sum += __shfl_xor_sync(0xFFFFFFFFu, sum, o);
            if (lane == 0) s_sc[j] = sum + bias;
        }
    }
    __syncthreads();

    // split-local max
    if (tid < 128) red[tid] = (tid < nv) ? s_sc[tid] : -1e30f;
    __syncthreads();
#pragma unroll
    for (int o = 64; o > 0; o >>= 1) {
        if (tid < o) red[tid] = fmaxf(red[tid], red[tid + o]);
        __syncthreads();
    }
    float m_s = red[0];
    __syncthreads();
    if (tid < nv) {
        float sc = s_sc[tid];
        s_wt[tid] = __expf(sc - m_s);
        g_score[(l0 + s_list[tid]) * B_DIM + b] = sc;
    }
    // split-local Z
    if (tid < 128) red[tid] = (tid < nv) ? __expf(s_sc[tid] - m_s) : 0.0f;
    __syncthreads();
#pragma unroll
    for (int o = 64; o > 0; o >>= 1) {
        if (tid < o) red[tid] += red[tid + o];
        __syncthreads();
    }
    if (tid == 0) {
        g_m[s * B_DIM + b] = m_s;
        g_z[s * B_DIM + b] = red[0];
    }
    __syncthreads();

    float4 acc = make_float4(0.f, 0.f, 0.f, 0.f);
    const float4* base = (const float4*)xs_h;
    const size_t stride = (size_t)B_DIM * (D_ENC / 4);
    size_t rowbase = ((size_t)(l0 * B_DIM + b)) * (D_ENC / 4) + tid;
    int j = 0;
    for (; j + 3 < nv; j += 4) {
        int i0 = s_list[j], i1 = s_list[j + 1], i2 = s_list[j + 2], i3 = s_list[j + 3];
        float4 v0 = ldcs4(base + rowbase + (size_t)i0 * stride);
        float4 v1 = ldcs4(base + rowbase + (size_t)i1 * stride);
        float4 v2 = ldcs4(base + rowbase + (size_t)i2 * stride);
        float4 v3 = ldcs4(base + rowbase + (size_t)i3 * stride);
        float w0 = s_wt[j], w1 = s_wt[j + 1], w2 = s_wt[j + 2], w3 = s_wt[j + 3];
        acc.x = fmaf(w0, v0.x, acc.x); acc.y = fmaf(w0, v0.y, acc.y);
        acc.z = fmaf(w0, v0.z, acc.z); acc.w = fmaf(w0, v0.w, acc.w);
        acc.x = fmaf(w1, v1.x, acc.x); acc.y = fmaf(w1, v1.y, acc.y);
        acc.z = fmaf(w1, v1.z, acc.z); acc.w = fmaf(w1, v1.w, acc.w);
        acc.x = fmaf(w2, v2.x, acc.x); acc.y = fmaf(w2, v2.y, acc.y);
        acc.z = fmaf(w2, v2.z, acc.z); acc.w = fmaf(w2, v2.w, acc.w);
        acc.x = fmaf(w3, v3.x, acc.x); acc.y = fmaf(w3, v3.y, acc.y);
        acc.z = fmaf(w3, v3.z, acc.z); acc.w = fmaf(w3, v3.w, acc.w);
    }
    for (; j < nv; j++) {
        float4 v = ldcs4(base + rowbase + (size_t)s_list[j] * stride);
        float w = s_wt[j];
        acc.x = fmaf(w, v.x, acc.x); acc.y = fmaf(w, v.y, acc.y);
        acc.z = fmaf(w, v.z, acc.z); acc.w = fmaf(w, v.w, acc.w);
    }
    ((float4*)g_partial)[((s * B_DIM + b) * (D_ENC / 4)) + tid] = acc;
}

// ---- Kernel 3a: tiny per-b stats combine from split (m_s, z_s) ----
__global__ __launch_bounds__(64) void k_stats() {
    int b = threadIdx.x;   // 0..63, single block
    float m = -1e30f;
#pragma unroll
    for (int s = 0; s < N_SPLIT; s++) m = fmaxf(m, g_m[s * B_DIM + b]);
    float z = 0.0f;
#pragma unroll
    for (int s = 0; s < N_SPLIT; s++)
        z += g_z[s * B_DIM + b] * __expf(g_m[s * B_DIM + b] - m);
    g_stats[b] = make_float2(m, 1.0f / z);
}

// ---- Kernel 3b: write — e_ij (coalesced scalar, blocks 0..511) and attend
//      (blocks 512..767: 4 blocks per b, 4 splits per thread + smem combine) ----
__global__ __launch_bounds__(256) void k_write(const float* __restrict__ xs_mask,
                                               float* __restrict__ out) {
    int t = blockIdx.x;
    int tid = threadIdx.x;
    if (t < EW_BLOCKS) {
        // coalesced: idx runs linearly over [L, B]
        int idx = t * 256 + tid;
        int b = idx & (B_DIM - 1);
        float2 st = g_stats[b];
        float msk = xs_mask[idx];
        float e = 0.0f;
        if (msk > 0.0f) e = __expf(g_score[idx] - st.x) * st.y;
        out[idx] = e;
    } else {
        // attend: block (b, q) covers float4 cols q*64..q*64+63 of row b.
        // thread = (sgroup = tid>>6, col64 = tid&63); each accumulates 4 splits.
        __shared__ float4 sm[256];
        int a = t - EW_BLOCKS;
        int b = a >> 2, q = a & 3;
        int col = q * 64 + (tid & 63);
        int sg = tid >> 6;             // 0..3 -> splits sg*4 .. sg*4+3
        float2 st = g_stats[b];
        float m = st.x, inv = st.y;
        float4 acc = make_float4(0.f, 0.f, 0.f, 0.f);
#pragma unroll
        for (int k = 0; k < 4; k++) {
            int s = sg * 4 + k;
            float f = __expf(g_m[s * B_DIM + b] - m);
            float4 v = ((const float4*)g_partial)[((s * B_DIM + b) * (D_ENC / 4)) + col];
            acc.x = fmaf(f, v.x, acc.x);
            acc.y = fmaf(f, v.y, acc.y);
            acc.z = fmaf(f, v.z, acc.z);
            acc.w = fmaf(f, v.w, acc.w);
        }
        sm[tid] = acc;
        __syncthreads();
        if (tid < 64) {
            float4 a0 = sm[tid];
            float4 a1 = sm[tid + 64];
            float4 a2 = sm[tid + 128];
            float4 a3 = sm[tid + 192];
            float4 r;
            r.x = (((a0.x + a1.x) + a2.x) + a3.x) * inv;
            r.y = (((a0.y + a1.y) + a2.y) + a3.y) * inv;
            r.z = (((a0.z + a1.z) + a2.z) + a3.z) * inv;
            r.w = (((a0.w + a1.w) + a2.w) + a3.w) * inv;
            ((float4*)(out + L_DIM * B_DIM))[b * (D_ENC / 4) + q * 64 + tid] = r;
        }
    }
}

extern "C" void kernel_launch(void* const* d_in, const int* in_sizes, int n_in,
                              void* d_out, int out_size) {
    const float* s_tm1   = (const float*)d_in[0];
    const float* xs_h    = (const float*)d_in[1];
    const float* uh      = (const float*)d_in[2];
    const float* xs_mask = (const float*)d_in[3];
    const float* sa_w    = (const float*)d_in[4];
    const float* sa_b    = (const float*)d_in[5];
    const float* a1_w    = (const float*)d_in[6];
    const float* a1_b    = (const float*)d_in[7];
    float* out = (float*)d_out;

    dim3 g1(16, 8, K_SPLIT);
    k_projp<<<g1, 256>>>(s_tm1, sa_w);
    dim3 g2(N_SPLIT, B_DIM);
    k_fused<<<g2, 256>>>(uh, sa_b, a1_w, a1_b, xs_mask, xs_h);
    k_stats<<<1, 64>>>();
    k_write<<<EW_BLOCKS + AT_BLOCKS, 256>>>(xs_mask, out);
}